// round 17
// baseline (speedup 1.0000x reference)
#include <cuda_runtime.h>
#include <cuda_bf16.h>
#include <cstdint>

// DWT_1D haar: lfc[k] = l0*x[2k] + l1*x[2k+1]; hfc[k] = h0*x[2k] + h1*x[2k+1]
// (coefficients read from matrix_low[0..1] / matrix_high[0..1]).
// Pure streaming (64 MiB in, 64 MiB out).
//
// Warp-specialized producer/consumer pipeline (race-free):
//   - warp 8 (threads 256..287) is the PRODUCER: wait empty[s] -> expect_tx ->
//     cp.async.bulk. It runs independently of consumer program order, so the
//     refill issues the moment a buffer is released (R11/R15 serialized this
//     behind tid0's compute and lost 6us).
//   - warps 0..7 are CONSUMERS: wait full[s] -> compute from smem -> __stcs
//     stores -> one elected release-arrive per warp on empty[s].
// 2 stages x 16 KiB chunks (verified-best grain). Stores __stcs (write-once).

#define CHUNK_F4    1024                // float4 per chunk = 16 KiB
#define CHUNK_BYTES 16384
#define OUT_F4      512                 // float4 outputs per side per chunk
#define CONSUMERS   256
#define NTHREADS    288                 // 8 consumer warps + 1 producer warp
#define STAGES      2

__device__ __forceinline__ uint32_t smem_u32(const void* p) {
    uint32_t a;
    asm("{ .reg .u64 t; cvta.to.shared.u64 t, %1; cvt.u32.u64 %0, t; }"
        : "=r"(a) : "l"(p));
    return a;
}

__device__ __forceinline__ void mbar_init(uint32_t mbar, uint32_t count) {
    asm volatile("mbarrier.init.shared.b64 [%0], %1;" :: "r"(mbar), "r"(count) : "memory");
}

__device__ __forceinline__ void mbar_arrive_release(uint32_t mbar) {
    asm volatile("mbarrier.arrive.release.cta.shared::cta.b64 _, [%0];"
                 :: "r"(mbar) : "memory");
}

__device__ __forceinline__ void mbar_expect_tx(uint32_t mbar, uint32_t bytes) {
    asm volatile("mbarrier.arrive.expect_tx.shared.b64 _, [%0], %1;"
                 :: "r"(mbar), "r"(bytes) : "memory");
}

__device__ __forceinline__ void mbar_wait(uint32_t mbar, uint32_t parity) {
    asm volatile(
        "{\n\t"
        ".reg .pred P;\n\t"
        "WAIT_%=:\n\t"
        "mbarrier.try_wait.parity.acquire.cta.shared::cta.b64 P, [%0], %1, 0x989680;\n\t"
        "@P bra.uni DONE_%=;\n\t"
        "bra.uni WAIT_%=;\n\t"
        "DONE_%=:\n\t"
        "}"
        :: "r"(mbar), "r"(parity) : "memory");
}

__device__ __forceinline__ void bulk_ld(uint32_t dst_smem, const void* src_gmem,
                                        uint32_t bytes, uint32_t mbar) {
    asm volatile(
        "cp.async.bulk.shared::cta.global.mbarrier::complete_tx::bytes [%0], [%1], %2, [%3];"
        :: "r"(dst_smem), "l"(src_gmem), "r"(bytes), "r"(mbar) : "memory");
}

__global__ void __launch_bounds__(NTHREADS) dwt1d_haar_ws_kernel(
    const float4* __restrict__ x4,
    const float* __restrict__ ml,
    const float* __restrict__ mh,
    float4* __restrict__ out_low,
    float4* __restrict__ out_high,
    int nchunks)
{
    __shared__ __align__(16) float4 buf[STAGES][CHUNK_F4];     // 2 x 16 KiB
    __shared__ __align__(8) unsigned long long full_store[STAGES];
    __shared__ __align__(8) unsigned long long empty_store[STAGES];

    const int tid  = threadIdx.x;
    const int wid  = tid >> 5;
    const int lane = tid & 31;

    uint32_t full_mb[STAGES], empty_mb[STAGES], bufa[STAGES];
    #pragma unroll
    for (int s = 0; s < STAGES; s++) {
        full_mb[s]  = smem_u32(&full_store[s]);
        empty_mb[s] = smem_u32(&empty_store[s]);
        bufa[s]     = smem_u32(&buf[s][0]);
    }

    if (tid == 0) {
        #pragma unroll
        for (int s = 0; s < STAGES; s++) {
            mbar_init(full_mb[s], 1);   // tx-based completion
            mbar_init(empty_mb[s], 8);  // one elected arrive per consumer warp
        }
    }
    __syncthreads();   // init visible before any arrive/wait/TMA

    if (wid == 8) {
        // ───────── producer warp ─────────
        if (lane == 0) {
            uint32_t phase = 1;   // first empty-wait passes immediately
            for (int k = 0;; ++k) {
                int c = blockIdx.x + k * gridDim.x;
                if (c >= nchunks) break;
                const int stage = k & 1;
                mbar_wait(empty_mb[stage], phase);
                mbar_expect_tx(full_mb[stage], CHUNK_BYTES);
                bulk_ld(bufa[stage], x4 + (size_t)c * CHUNK_F4, CHUNK_BYTES,
                        full_mb[stage]);
                if (stage == 1) phase ^= 1;   // wrapped
            }
        }
    } else {
        // ───────── consumer warps ─────────
        const float l0 = ml[0], l1 = ml[1];
        const float h0 = mh[0], h1 = mh[1];

        for (int k = 0;; ++k) {
            int c = blockIdx.x + k * gridDim.x;
            if (c >= nchunks) break;

            const int stage = k & 1;
            const uint32_t par = (k >> 1) & 1;

            mbar_wait(full_mb[stage], par);
            const float4* __restrict__ s = buf[stage];

            float4 a0 = s[2 * tid];
            float4 a1 = s[2 * tid + 1];
            float4 b0 = s[2 * (tid + CONSUMERS)];
            float4 b1 = s[2 * (tid + CONSUMERS) + 1];

            const int base = c * OUT_F4;
            float4 lo, hi;
            lo.x = l0 * a0.x + l1 * a0.y;  hi.x = h0 * a0.x + h1 * a0.y;
            lo.y = l0 * a0.z + l1 * a0.w;  hi.y = h0 * a0.z + h1 * a0.w;
            lo.z = l0 * a1.x + l1 * a1.y;  hi.z = h0 * a1.x + h1 * a1.y;
            lo.w = l0 * a1.z + l1 * a1.w;  hi.w = h0 * a1.z + h1 * a1.w;
            __stcs(&out_low[base + tid],  lo);
            __stcs(&out_high[base + tid], hi);

            lo.x = l0 * b0.x + l1 * b0.y;  hi.x = h0 * b0.x + h1 * b0.y;
            lo.y = l0 * b0.z + l1 * b0.w;  hi.y = h0 * b0.z + h1 * b0.w;
            lo.z = l0 * b1.x + l1 * b1.y;  hi.z = h0 * b1.x + h1 * b1.y;
            lo.w = l0 * b1.z + l1 * b1.w;  hi.w = h0 * b1.z + h1 * b1.w;
            __stcs(&out_low[base + tid + CONSUMERS],  lo);
            __stcs(&out_high[base + tid + CONSUMERS], hi);

            // Release the buffer: smem reads are ordered by the release-arrive.
            __syncwarp();
            if (lane == 0) mbar_arrive_release(empty_mb[stage]);
        }
    }
}

extern "C" void kernel_launch(void* const* d_in, const int* in_sizes, int n_in,
                              void* d_out, int out_size) {
    const float* x  = (const float*)d_in[0];   // [32,64,8192] f32
    const float* ml = (const float*)d_in[1];   // [4096,8192] f32
    const float* mh = (const float*)d_in[2];   // [4096,8192] f32
    float* out = (float*)d_out;                // [lfc | hfc]

    const int in_elems = in_sizes[0];          // 16777216
    const int half = out_size / 2;             // 8388608 lfc elements
    const int nchunks = in_elems / (CHUNK_F4 * 4);   // 4096
    (void)n_in;

    const int grid = 1024;                     // 4 chunks per CTA exactly

    dwt1d_haar_ws_kernel<<<grid, NTHREADS>>>(
        (const float4*)x, ml, mh,
        (float4*)out, (float4*)(out + half),
        nchunks);
}